// round 6
// baseline (speedup 1.0000x reference)
#include <cuda_runtime.h>
#include <math.h>

// Problem constants
#define CV 10000
#define CE 512
#define CH 1024
#define CK 2048
#define CB 64
#define CS 196
#define CT 15

// ---------------- scratch layout (floats) ----------------
#define OFF_XEMB   0u            // 960*512
#define OFF_XSEQT  491520u       // [1024][960]
#define OFF_KEYS   1474560u      // 12544*1024
#define OFF_E      14319616u     // 12544
#define OFF_W      14332160u     // 12544
#define OFF_QP     14344704u     // 8*64*1024
#define OFF_QS     14868992u     // 64*1024
#define OFF_CTXT   14934528u     // [2048][64]
#define OFF_CTXH   15065600u     // [1024][64]
#define OFF_HA     15131136u     // 4*1024*64
#define OFF_HB     15393280u     // 4*1024*64
#define OFF_FC0P   15655424u     // 8*1024*64
#define OFF_FC2P   16179712u     // 2*64*10016
#define OFF_WQT    17461760u     // 1024*1024
#define OFF_FC0T   18510336u     // [1024][2048]
#define OFF_FC2T   20607488u     // [10000][1024]
#define OFF_GIX    30847488u     // [3072][960]
#define SCRATCH_TOTAL 33796608u

__device__ __align__(16) float g_scratch[SCRATCH_TOTAL];

__device__ __forceinline__ float fast_tanh(float x) {
    float e = __expf(2.0f * x);
    return 1.0f - __fdividef(2.0f, 1.0f + e);
}

__device__ __forceinline__ float tf32r(float x) {
    unsigned u;
    asm("cvt.rna.tf32.f32 %0, %1;" : "=r"(u) : "f"(x));
    return __uint_as_float(u);
}

__device__ __forceinline__ void mma8(float* c, const unsigned* a, const unsigned* b) {
    asm volatile(
        "mma.sync.aligned.m16n8k8.row.col.f32.tf32.tf32.f32 "
        "{%0,%1,%2,%3}, {%4,%5,%6,%7}, {%8,%9}, {%0,%1,%2,%3};\n"
        : "+f"(c[0]), "+f"(c[1]), "+f"(c[2]), "+f"(c[3])
        : "r"(a[0]), "r"(a[1]), "r"(a[2]), "r"(a[3]), "r"(b[0]), "r"(b[1]));
}

// ---------------- tf32 tensor-core GEMM (128x64x32 tile, 8 warps) ----------------
// C[m,n] = sum_k A[m,k]*B[k,n]; split-K over gridDim.z -> C + z*zstride.
// STORE_T: C[col*ldc + row]; else C[row*ldc + col]. Bias applied in both paths.
template<bool STORE_T>
__global__ void __launch_bounds__(256)
gemm_tf32(const float* __restrict__ A, const float* __restrict__ B,
          const float* __restrict__ bias, float* __restrict__ C,
          int M, int K, int lda, int ldb, int ldc, size_t zstride)
{
    __shared__ float As[128 * 44];
    __shared__ float Bs[32 * 72];

    int tid = threadIdx.x;
    int lane = tid & 31, w = tid >> 5;
    int wm = (w & 3) * 32, wn = (w >> 2) * 32;
    int bn = blockIdx.x * 64, bm = blockIdx.y * 128;
    int kper = K / gridDim.z;
    int k0 = blockIdx.z * kper, kend = k0 + kper;
    C += (size_t)blockIdx.z * zstride;

    float acc[2][4][4] = {};
    float4 apf[4], bpf[2];

    {
        int kc = k0;
#pragma unroll
        for (int i = 0; i < 4; i++) {
            int f = tid + i * 256, m = f >> 3, k4 = f & 7;
            int gm = bm + m; if (gm >= M) gm = M - 1;
            apf[i] = *(const float4*)(A + (size_t)gm * lda + kc + k4 * 4);
        }
#pragma unroll
        for (int i = 0; i < 2; i++) {
            int f = tid + i * 256, kr = f >> 4, n4 = f & 15;
            bpf[i] = *(const float4*)(B + (size_t)(kc + kr) * ldb + bn + n4 * 4);
        }
    }

    for (int kc = k0; kc < kend; kc += 32) {
#pragma unroll
        for (int i = 0; i < 4; i++) {
            int f = tid + i * 256, m = f >> 3, k4 = f & 7;
            float4 v = apf[i];
            *(float4*)&As[m * 44 + k4 * 4] =
                make_float4(tf32r(v.x), tf32r(v.y), tf32r(v.z), tf32r(v.w));
        }
#pragma unroll
        for (int i = 0; i < 2; i++) {
            int f = tid + i * 256, kr = f >> 4, n4 = f & 15;
            float4 v = bpf[i];
            *(float4*)&Bs[kr * 72 + n4 * 4] =
                make_float4(tf32r(v.x), tf32r(v.y), tf32r(v.z), tf32r(v.w));
        }
        __syncthreads();
        if (kc + 32 < kend) {
            int kn = kc + 32;
#pragma unroll
            for (int i = 0; i < 4; i++) {
                int f = tid + i * 256, m = f >> 3, k4 = f & 7;
                int gm = bm + m; if (gm >= M) gm = M - 1;
                apf[i] = *(const float4*)(A + (size_t)gm * lda + kn + k4 * 4);
            }
#pragma unroll
            for (int i = 0; i < 2; i++) {
                int f = tid + i * 256, kr = f >> 4, n4 = f & 15;
                bpf[i] = *(const float4*)(B + (size_t)(kn + kr) * ldb + bn + n4 * 4);
            }
        }
        const unsigned* Asu = (const unsigned*)As;
        const unsigned* Bsu = (const unsigned*)Bs;
        int r = lane >> 2, cq = lane & 3;
#pragma unroll
        for (int kk = 0; kk < 4; kk++) {
            unsigned a[2][4], bf[4][2];
#pragma unroll
            for (int t = 0; t < 2; t++) {
                int base = (wm + t * 16 + r) * 44 + kk * 8 + cq;
                a[t][0] = Asu[base];
                a[t][1] = Asu[base + 8 * 44];
                a[t][2] = Asu[base + 4];
                a[t][3] = Asu[base + 8 * 44 + 4];
            }
#pragma unroll
            for (int j = 0; j < 4; j++) {
                int base = (kk * 8 + cq) * 72 + wn + j * 8 + r;
                bf[j][0] = Bsu[base];
                bf[j][1] = Bsu[base + 4 * 72];
            }
#pragma unroll
            for (int t = 0; t < 2; t++)
#pragma unroll
                for (int j = 0; j < 4; j++)
                    mma8(acc[t][j], a[t], bf[j]);
        }
        __syncthreads();
    }

    int r = lane >> 2, cq = lane & 3;
#pragma unroll
    for (int t = 0; t < 2; t++) {
#pragma unroll
        for (int j = 0; j < 4; j++) {
            int row0 = bm + wm + t * 16 + r;
            int col = bn + wn + j * 8 + cq * 2;
            float* ac = acc[t][j];
            float b0 = bias ? bias[col] : 0.0f;
            float b1 = bias ? bias[col + 1] : 0.0f;
            if (STORE_T) {
                if (row0 < M) {
                    C[(size_t)col * ldc + row0] = ac[0] + b0;
                    C[(size_t)(col + 1) * ldc + row0] = ac[1] + b1;
                }
                if (row0 + 8 < M) {
                    C[(size_t)col * ldc + row0 + 8] = ac[2] + b0;
                    C[(size_t)(col + 1) * ldc + row0 + 8] = ac[3] + b1;
                }
            } else {
                if (row0 < M)
                    *(float2*)(C + (size_t)row0 * ldc + col) = make_float2(ac[0] + b0, ac[1] + b1);
                if (row0 + 8 < M)
                    *(float2*)(C + (size_t)(row0 + 8) * ldc + col) = make_float2(ac[2] + b0, ac[3] + b1);
            }
        }
    }
}

// ---------------- fused GRU layer: gi = Wi@x, gh = Wh@h, update in epilogue ----
// Block: 48 rows (3 gates x 16 j) x 32 batch, K=1024. Grid: 128 blocks.
// 6 warps, warp tile 16x16 for both GEMMs. hin read-only; hout written (ping-pong).
__global__ void __launch_bounds__(192)
gru_fused(const float* __restrict__ Wi, int ldwi,
          const float* __restrict__ Wh,
          const float* __restrict__ x,     // [1024][64]
          const float* __restrict__ hin,   // [1024][64]
          float* __restrict__ hout,        // [1024][64]
          const float* __restrict__ gix,   // [3072][960] at col offset, or null
          const float* __restrict__ bi, const float* __restrict__ bh)
{
    __shared__ float As[2 * 48 * 36];   // [mat][row][k], stride 36
    __shared__ float Bs[2 * 32 * 36];   // [mat][k][n], stride 36

    int tid = threadIdx.x;
    int lane = tid & 31, w = tid >> 5;
    int J0 = (blockIdx.x >> 1) * 16;
    int B0 = (blockIdx.x & 1) * 32;
    int g = w >> 1, nh = w & 1;

    float accI[2][4] = {}, accH[2][4] = {};
    float4 pf[7];

    // prefetch chunk 0
#pragma unroll
    for (int i = 0; i < 7; i++) {
        int f = tid + i * 192;
        if (f < 768) {
            int mat = f >= 384; int ff = f - mat * 384;   // FIX: 384 not pow2, no mask
            int row = ff >> 3, k4 = ff & 7;
            int grow = ((row >> 4) << 10) + J0 + (row & 15);
            const float* src = mat ? (Wh + (size_t)grow * 1024) : (Wi + (size_t)grow * ldwi);
            pf[i] = *(const float4*)(src + k4 * 4);
        } else if (f < 1280) {
            int ff = f - 768; int mat = ff >= 256; int fb = ff & 255;
            int kr = fb >> 3, n4 = fb & 7;
            const float* src = (mat ? hin : x) + (size_t)kr * 64 + B0 + n4 * 4;
            pf[i] = *(const float4*)src;
        }
    }

    int r = lane >> 2, cq = lane & 3;
    for (int kc = 0; kc < 1024; kc += 32) {
        // STS with tf32 rounding
#pragma unroll
        for (int i = 0; i < 7; i++) {
            int f = tid + i * 192;
            float4 v = pf[i];
            float4 cv = make_float4(tf32r(v.x), tf32r(v.y), tf32r(v.z), tf32r(v.w));
            if (f < 768) {
                int mat = f >= 384; int ff = f - mat * 384;   // FIX
                int row = ff >> 3, k4 = ff & 7;
                *(float4*)&As[mat * (48 * 36) + row * 36 + k4 * 4] = cv;
            } else if (f < 1280) {
                int ff = f - 768; int mat = ff >= 256; int fb = ff & 255;
                int kr = fb >> 3, n4 = fb & 7;
                *(float4*)&Bs[mat * (32 * 36) + kr * 36 + n4 * 4] = cv;
            }
        }
        __syncthreads();
        if (kc + 32 < 1024) {
            int kn = kc + 32;
#pragma unroll
            for (int i = 0; i < 7; i++) {
                int f = tid + i * 192;
                if (f < 768) {
                    int mat = f >= 384; int ff = f - mat * 384;   // FIX
                    int row = ff >> 3, k4 = ff & 7;
                    int grow = ((row >> 4) << 10) + J0 + (row & 15);
                    const float* src = mat ? (Wh + (size_t)grow * 1024) : (Wi + (size_t)grow * ldwi);
                    pf[i] = *(const float4*)(src + kn + k4 * 4);
                } else if (f < 1280) {
                    int ff = f - 768; int mat = ff >= 256; int fb = ff & 255;
                    int kr = fb >> 3, n4 = fb & 7;
                    const float* src = (mat ? hin : x) + (size_t)(kn + kr) * 64 + B0 + n4 * 4;
                    pf[i] = *(const float4*)src;
                }
            }
        }
        const unsigned* Au = (const unsigned*)As;
        const unsigned* Bu = (const unsigned*)Bs;
#pragma unroll
        for (int kk = 0; kk < 4; kk++) {
            unsigned ai[4], ah[4];
            int abase = (g * 16 + r) * 36 + kk * 8 + cq;
            ai[0] = Au[abase];             ai[1] = Au[abase + 8 * 36];
            ai[2] = Au[abase + 4];         ai[3] = Au[abase + 8 * 36 + 4];
            ah[0] = Au[48 * 36 + abase];   ah[1] = Au[48 * 36 + abase + 8 * 36];
            ah[2] = Au[48 * 36 + abase + 4]; ah[3] = Au[48 * 36 + abase + 8 * 36 + 4];
            unsigned bx[2][2], bh2[2][2];
#pragma unroll
            for (int j = 0; j < 2; j++) {
                int bbase = (kk * 8 + cq) * 36 + nh * 16 + j * 8 + r;
                bx[j][0] = Bu[bbase];            bx[j][1] = Bu[bbase + 4 * 36];
                bh2[j][0] = Bu[32 * 36 + bbase]; bh2[j][1] = Bu[32 * 36 + bbase + 4 * 36];
            }
#pragma unroll
            for (int j = 0; j < 2; j++) { mma8(accI[j], ai, bx[j]); mma8(accH[j], ah, bh2[j]); }
        }
        __syncthreads();
    }

    // epilogue: stage gi/gh into smem, then elementwise GRU update
    float* gi_s = As;            // [48][32]
    float* gh_s = As + 1536;     // [48][32]
#pragma unroll
    for (int j = 0; j < 2; j++) {
        int row0 = g * 16 + r;
        int col = nh * 16 + j * 8 + cq * 2;
        gi_s[row0 * 32 + col] = accI[j][0];       gi_s[row0 * 32 + col + 1] = accI[j][1];
        gi_s[(row0 + 8) * 32 + col] = accI[j][2]; gi_s[(row0 + 8) * 32 + col + 1] = accI[j][3];
        gh_s[row0 * 32 + col] = accH[j][0];       gh_s[row0 * 32 + col + 1] = accH[j][1];
        gh_s[(row0 + 8) * 32 + col] = accH[j][2]; gh_s[(row0 + 8) * 32 + col + 1] = accH[j][3];
    }
    __syncthreads();
    for (int idx = tid; idx < 512; idx += 192) {
        int jj = idx >> 5, bb = idx & 31;
        int j = J0 + jj, b = B0 + bb;
        float ir = gi_s[jj * 32 + bb] + bi[j];
        float iz = gi_s[(16 + jj) * 32 + bb] + bi[1024 + j];
        float in_ = gi_s[(32 + jj) * 32 + bb] + bi[2048 + j];
        if (gix) {
            ir  += gix[(size_t)j * 960 + b];
            iz  += gix[(size_t)(1024 + j) * 960 + b];
            in_ += gix[(size_t)(2048 + j) * 960 + b];
        }
        float hr = gh_s[jj * 32 + bb] + bh[j];
        float hz = gh_s[(16 + jj) * 32 + bb] + bh[1024 + j];
        float hn = gh_s[(32 + jj) * 32 + bb] + bh[2048 + j];
        float rr = 1.0f / (1.0f + expf(-(ir + hr)));
        float zz = 1.0f / (1.0f + expf(-(iz + hz)));
        float nn = tanhf(in_ + rr * hn);
        float hold = hin[(size_t)j * 64 + b];
        hout[(size_t)j * 64 + b] = (1.0f - zz) * nn + zz * hold;
    }
}

// ---------------- misc kernels ----------------
__global__ void zerok(float* p, int n) {
    int i = blockIdx.x * 256 + threadIdx.x;
    if (i < n) p[i] = 0.0f;
}

// xemb row m' = t*64 + b
__global__ void gather_emb(const float* __restrict__ emb,
                           const int* __restrict__ captions,
                           const int* __restrict__ sos,
                           float* __restrict__ xemb) {
    int m = blockIdx.x;
    int b = m & 63, t = m >> 6;
    int tok = (t == 0) ? sos[0] : captions[b * 16 + t];
    const float4* src = (const float4*)(emb + (size_t)tok * CE);
    float4* dst = (float4*)(xemb + (size_t)m * CE);
    dst[threadIdx.x] = src[threadIdx.x];
}

__global__ void transpose_k(const float* __restrict__ in, float* __restrict__ out,
                            int R, int Cc) {
    __shared__ float t[32][33];
    int c = blockIdx.x * 32 + threadIdx.x;
    int r = blockIdx.y * 32 + threadIdx.y;
#pragma unroll
    for (int i = 0; i < 4; i++) {
        int rr = r + i * 8;
        if (rr < R && c < Cc) t[threadIdx.y + i * 8][threadIdx.x] = in[(size_t)rr * Cc + c];
    }
    __syncthreads();
    int c2 = blockIdx.y * 32 + threadIdx.x;
    int r2 = blockIdx.x * 32 + threadIdx.y;
#pragma unroll
    for (int i = 0; i < 4; i++) {
        int rr = r2 + i * 8;
        if (rr < Cc && c2 < R) out[(size_t)rr * R + c2] = t[threadIdx.x][threadIdx.y + i * 8];
    }
}

__global__ void qsum_kernel(const float* __restrict__ qp, const float* __restrict__ bq,
                            float* __restrict__ qs) {
    int idx = blockIdx.x * 256 + threadIdx.x;
    int h = idx & 1023;
    float s = bq[h];
#pragma unroll
    for (int z = 0; z < 8; z++) s += qp[z * (CB * CH) + idx];
    qs[idx] = s;
}

// e[b,s] = bv + sum_h v[h]*tanh(qs[b,h] + keys[b,s,h]), float4 vectorized
__global__ void e_kernel(const float* __restrict__ qs, const float* __restrict__ keys,
                         const float* __restrict__ v, const float* __restrict__ bv,
                         float* __restrict__ e) {
    int s = blockIdx.x, b = blockIdx.y, tid = threadIdx.x;
    const float4* krow = (const float4*)(keys + ((size_t)b * CS + s) * CH);
    const float4* qrow = (const float4*)(qs + (size_t)b * CH);
    const float4* v4 = (const float4*)v;
    float partial = 0.0f;
#pragma unroll
    for (int i = 0; i < 2; i++) {
        int idx = tid + i * 128;
        float4 k4 = krow[idx], q4 = qrow[idx], vv = v4[idx];
        partial += vv.x * fast_tanh(q4.x + k4.x);
        partial += vv.y * fast_tanh(q4.y + k4.y);
        partial += vv.z * fast_tanh(q4.z + k4.z);
        partial += vv.w * fast_tanh(q4.w + k4.w);
    }
#pragma unroll
    for (int o = 16; o > 0; o >>= 1) partial += __shfl_xor_sync(0xffffffffu, partial, o);
    __shared__ float ws[4];
    if ((tid & 31) == 0) ws[tid >> 5] = partial;
    __syncthreads();
    if (tid == 0) e[b * CS + s] = ws[0] + ws[1] + ws[2] + ws[3] + bv[0];
}

__global__ void softmax_k(const float* __restrict__ e, float* __restrict__ w) {
    int b = blockIdx.x, tid = threadIdx.x;
    __shared__ float sh[256];
    float v = (tid < CS) ? e[b * CS + tid] : -1e30f;
    sh[tid] = v; __syncthreads();
    for (int o = 128; o > 0; o >>= 1) { if (tid < o) sh[tid] = fmaxf(sh[tid], sh[tid + o]); __syncthreads(); }
    float m = sh[0]; __syncthreads();
    float ex = (tid < CS) ? __expf(v - m) : 0.0f;
    sh[tid] = ex; __syncthreads();
    for (int o = 128; o > 0; o >>= 1) { if (tid < o) sh[tid] += sh[tid + o]; __syncthreads(); }
    float s = sh[0];
    if (tid < CS) w[b * CS + tid] = ex / s;
}

__global__ void ctx_kernel(const float* __restrict__ w, const float* __restrict__ feat,
                           float* __restrict__ ctxT) {
    int kk = threadIdx.x & 31, bb = threadIdx.x >> 5;
    int b = blockIdx.y * 8 + bb;
    int k = blockIdx.x * 32 + kk;
    __shared__ float ws[8][200];
    for (int i = threadIdx.x; i < 8 * CS; i += 256)
        ws[i / CS][i % CS] = w[(blockIdx.y * 8 + i / CS) * CS + i % CS];
    __syncthreads();
    const float* f = feat + ((size_t)b * CS) * CK + k;
    float acc = 0.0f;
#pragma unroll 4
    for (int s = 0; s < CS; s++) acc = fmaf(ws[bb][s], f[(size_t)s * CK], acc);
    ctxT[k * CB + b] = acc;
}

__global__ void reduce64(const float* __restrict__ part, const float* __restrict__ bias,
                         float* __restrict__ out, int z, size_t zstride) {
    int idx = blockIdx.x * 256 + threadIdx.x;
    int row = idx >> 6;
    float s = bias[row];
    for (int zz = 0; zz < z; zz++) s += part[zz * zstride + idx];
    out[idx] = s;
}

__global__ void reduce_fc2(const float* __restrict__ p, const float* __restrict__ bias,
                           float* __restrict__ out, int t) {
    int idx = blockIdx.x * 256 + threadIdx.x;
    if (idx >= CB * CV) return;
    int b = idx / CV, v = idx - b * CV;
    float s = bias[v] + p[(size_t)b * 10016 + v] + p[(size_t)CB * 10016 + (size_t)b * 10016 + v];
    out[((size_t)b * CT + t) * CV + v] = s;
}

// ---------------- host launcher ----------------
extern "C" void kernel_launch(void* const* d_in, const int* in_sizes, int n_in,
                              void* d_out, int out_size) {
    const float* features = (const float*)d_in[0];
    const int*   captions = (const int*)d_in[1];
    const int*   sos      = (const int*)d_in[2];
    const float* emb      = (const float*)d_in[3];
    const float* fc1_W    = (const float*)d_in[4];
    const float* fc1_b    = (const float*)d_in[5];
    const float* attn_Wq  = (const float*)d_in[6];
    const float* attn_bq  = (const float*)d_in[7];
    const float* attn_Wk  = (const float*)d_in[8];
    const float* attn_bk  = (const float*)d_in[9];
    const float* attn_v   = (const float*)d_in[10];
    const float* attn_bv  = (const float*)d_in[11];
    const float* fc0_W    = (const float*)d_in[12];
    const float* fc0_b    = (const float*)d_in[13];
    const float* Wi0      = (const float*)d_in[14];
    const float* Wh0      = (const float*)d_in[15];
    const float* bi0      = (const float*)d_in[16];
    const float* bh0      = (const float*)d_in[17];
    const float* WiL      = (const float*)d_in[18];
    const float* WhL      = (const float*)d_in[19];
    const float* biL      = (const float*)d_in[20];
    const float* bhL      = (const float*)d_in[21];
    const float* fc2_W    = (const float*)d_in[22];
    const float* fc2_b    = (const float*)d_in[23];
    float* out = (float*)d_out;

    float* sc = nullptr;
    cudaGetSymbolAddress((void**)&sc, g_scratch);
    float* xemb  = sc + OFF_XEMB;
    float* xseqT = sc + OFF_XSEQT;
    float* keys  = sc + OFF_KEYS;
    float* ebuf  = sc + OFF_E;
    float* wbuf  = sc + OFF_W;
    float* qp    = sc + OFF_QP;
    float* qs    = sc + OFF_QS;
    float* ctxT  = sc + OFF_CTXT;
    float* ctxH  = sc + OFF_CTXH;
    float* hA    = sc + OFF_HA;
    float* hB    = sc + OFF_HB;
    float* fc0p  = sc + OFF_FC0P;
    float* fc2p  = sc + OFF_FC2P;
    float* WqT   = sc + OFF_WQT;
    float* fc0T  = sc + OFF_FC0T;
    float* fc2T  = sc + OFF_FC2T;
    float* giX   = sc + OFF_GIX;

    zerok<<<(4 * CB * CH + 255) / 256, 256>>>(hA, 4 * CB * CH);
    gather_emb<<<CB * CT, 128>>>(emb, captions, sos, xemb);

    transpose_k<<<dim3(32, 32), dim3(32, 8)>>>(attn_Wq, WqT, CH, CH);
    transpose_k<<<dim3(32, 64), dim3(32, 8)>>>(fc0_W, fc0T, CK, CH);
    transpose_k<<<dim3((CV + 31) / 32, 32), dim3(32, 8)>>>(fc2_W, fc2T, CH, CV);

    // xseqT[h][t*64+b] = (xemb @ fc1_W + fc1_b)^T
    gemm_tf32<true><<<dim3(16, 8, 1), 256>>>(xemb, fc1_W, fc1_b, xseqT,
                                             960, CE, CE, CH, 960, 0);
    // giX = Wi0[:, :1024] @ xseqT  -> [3072][960]
    gemm_tf32<false><<<dim3(15, 24, 1), 256>>>(Wi0, xseqT, nullptr, giX,
                                               3 * CH, CH, 2 * CH, 960, 960, 0);
    // keys = features @ attn_Wk + attn_bk
    gemm_tf32<false><<<dim3(16, 98, 1), 256>>>(features, attn_Wk, attn_bk, keys,
                                               CB * CS, CK, CK, CH, CH, 0);

    for (int t = 0; t < CT; t++) {
        float* cur = (t & 1) ? hB : hA;
        float* nxt = (t & 1) ? hA : hB;
        float* htop = cur + 3 * CB * CH;       // state BEFORE update (query)
        float* htopNew = nxt + 3 * CB * CH;    // state AFTER update (logits)

        // q partials: WqT[1024][1024] @ htop[1024][64], STORE_T -> qp[z][b][h]
        gemm_tf32<true><<<dim3(1, 8, 8), 256>>>(WqT, htop, nullptr, qp,
                                                CH, CH, CH, CB, CH, (size_t)CB * CH);
        qsum_kernel<<<256, 256>>>(qp, attn_bq, qs);
        e_kernel<<<dim3(CS, CB), 128>>>(qs, keys, attn_v, attn_bv, ebuf);
        softmax_k<<<CB, 256>>>(ebuf, wbuf);
        ctx_kernel<<<dim3(CK / 32, 8), 256>>>(wbuf, features, ctxT);
        // fc0: fc0T[1024][2048] @ ctxT[2048][64] -> ctxH
        gemm_tf32<false><<<dim3(1, 8, 8), 256>>>(fc0T, ctxT, nullptr, fc0p,
                                                 CH, CK, CK, CB, CB, (size_t)CB * CH);
        reduce64<<<(CB * CH) / 256, 256>>>(fc0p, fc0_b, ctxH, 8, (size_t)CB * CH);
        // GRU layer 0 (Wi ctx-half, x-half precomputed in giX)
        gru_fused<<<128, 192>>>(Wi0 + CH, 2 * CH, Wh0, ctxH, cur, nxt,
                                giX + t * 64, bi0, bh0);
        // GRU layers 1..3
        for (int l = 1; l < 4; l++) {
            gru_fused<<<128, 192>>>(WiL + (size_t)(l - 1) * 3 * CH * CH, CH,
                                    WhL + (size_t)(l - 1) * 3 * CH * CH,
                                    nxt + (size_t)(l - 1) * CB * CH,
                                    cur + (size_t)l * CB * CH,
                                    nxt + (size_t)l * CB * CH,
                                    nullptr,
                                    biL + (size_t)(l - 1) * 3 * CH,
                                    bhL + (size_t)(l - 1) * 3 * CH);
        }
        // fc2: fc2T[10000][1024] @ htopNew, STORE_T -> fc2p[z][b][v]
        gemm_tf32<true><<<dim3(1, 79, 2), 256>>>(fc2T, htopNew, nullptr, fc2p,
                                                 CV, CH, CH, CB, 10016, (size_t)CB * 10016);
        reduce_fc2<<<(CB * CV + 255) / 256, 256>>>(fc2p, fc2_b, out, t);
    }
}

// round 7
// speedup vs baseline: 1.0911x; 1.0911x over previous
#include <cuda_runtime.h>
#include <cuda_fp16.h>
#include <math.h>

#define CV 10000
#define CE 512
#define CH 1024
#define CK 2048
#define CB 64
#define CS 196
#define CT 15

// ---------------- scratch layout (float units, 16B-aligned) ----------------
#define OFF_XEMB    0u          // 960*512
#define OFF_XSEQT   491520u     // [1024][960] f32
#define OFF_GIX     1474560u    // [3072][960] f32
#define OFF_KEYS16  4423680u    // 12544*1024 halves
#define OFF_FEAT16  10846208u   // 64*196*2048 halves
#define OFF_WQ16    23691264u   // [1024][1024] h
#define OFF_FC016   24215552u   // [1024][2048] h
#define OFF_FC216   25264128u   // [10000][1024] h
#define OFF_WI0C    30384128u   // [3072][1024] h
#define OFF_WH016   31956992u   // [3072][1024] h
#define OFF_WIL16   33529856u   // 3*[3072][1024] h
#define OFF_WHL16   38248448u   // 3*[3072][1024] h
#define OFF_E       42967040u
#define OFF_W       42979584u
#define OFF_QP      42992128u   // 8*[64][1024] f32
#define OFF_QS      43516416u   // [64][1024] f32
#define OFF_CTX16   43581952u   // [64][2048] h
#define OFF_CTXH16  43647488u   // [64][1024] h
#define OFF_H32A    43680256u   // 4*[1024][64] f32
#define OFF_H32B    43942400u
#define OFF_H16A    44204544u   // 4*[64][1024] h
#define OFF_H16B    44335616u
#define OFF_FC0P    44466688u   // 8*[1024][64] f32
#define OFF_FC2P    44990976u   // 2*[64][10016] f32
#define SCRATCH_TOTAL 46273024u

__device__ __align__(16) float g_scratch[SCRATCH_TOTAL];

__device__ __forceinline__ float fast_tanh(float x) {
    float e = __expf(2.0f * x);
    return 1.0f - __fdividef(2.0f, 1.0f + e);
}

__device__ __forceinline__ float tf32r(float x) {
    unsigned u;
    asm("cvt.rna.tf32.f32 %0, %1;" : "=r"(u) : "f"(x));
    return __uint_as_float(u);
}

__device__ __forceinline__ void mma8(float* c, const unsigned* a, const unsigned* b) {
    asm volatile(
        "mma.sync.aligned.m16n8k8.row.col.f32.tf32.tf32.f32 "
        "{%0,%1,%2,%3}, {%4,%5,%6,%7}, {%8,%9}, {%0,%1,%2,%3};\n"
        : "+f"(c[0]), "+f"(c[1]), "+f"(c[2]), "+f"(c[3])
        : "r"(a[0]), "r"(a[1]), "r"(a[2]), "r"(a[3]), "r"(b[0]), "r"(b[1]));
}

__device__ __forceinline__ void mma16(float* c, const unsigned* a, const unsigned* b) {
    asm volatile(
        "mma.sync.aligned.m16n8k16.row.col.f32.f16.f16.f32 "
        "{%0,%1,%2,%3}, {%4,%5,%6,%7}, {%8,%9}, {%0,%1,%2,%3};\n"
        : "+f"(c[0]), "+f"(c[1]), "+f"(c[2]), "+f"(c[3])
        : "r"(a[0]), "r"(a[1]), "r"(a[2]), "r"(a[3]), "r"(b[0]), "r"(b[1]));
}

// ---------------- tf32 GEMM (prologue; proven). HOUT: store fp16 ----------------
template<bool STORE_T, bool HOUT>
__global__ void __launch_bounds__(256)
gemm_tf32(const float* __restrict__ A, const float* __restrict__ B,
          const float* __restrict__ bias, float* __restrict__ C,
          int M, int K, int lda, int ldb, int ldc, size_t zstride)
{
    __shared__ float As[128 * 44];
    __shared__ float Bs[32 * 72];
    int tid = threadIdx.x;
    int lane = tid & 31, w = tid >> 5;
    int wm = (w & 3) * 32, wn = (w >> 2) * 32;
    int bn = blockIdx.x * 64, bm = blockIdx.y * 128;
    int kper = K / gridDim.z;
    int k0 = blockIdx.z * kper, kend = k0 + kper;
    C += (size_t)blockIdx.z * zstride;

    float acc[2][4][4] = {};
    float4 apf[4], bpf[2];
    {
        int kc = k0;
#pragma unroll
        for (int i = 0; i < 4; i++) {
            int f = tid + i * 256, m = f >> 3, k4 = f & 7;
            int gm = bm + m; if (gm >= M) gm = M - 1;
            apf[i] = *(const float4*)(A + (size_t)gm * lda + kc + k4 * 4);
        }
#pragma unroll
        for (int i = 0; i < 2; i++) {
            int f = tid + i * 256, kr = f >> 4, n4 = f & 15;
            bpf[i] = *(const float4*)(B + (size_t)(kc + kr) * ldb + bn + n4 * 4);
        }
    }
    for (int kc = k0; kc < kend; kc += 32) {
#pragma unroll
        for (int i = 0; i < 4; i++) {
            int f = tid + i * 256, m = f >> 3, k4 = f & 7;
            float4 v = apf[i];
            *(float4*)&As[m * 44 + k4 * 4] =
                make_float4(tf32r(v.x), tf32r(v.y), tf32r(v.z), tf32r(v.w));
        }
#pragma unroll
        for (int i = 0; i < 2; i++) {
            int f = tid + i * 256, kr = f >> 4, n4 = f & 15;
            float4 v = bpf[i];
            *(float4*)&Bs[kr * 72 + n4 * 4] =
                make_float4(tf32r(v.x), tf32r(v.y), tf32r(v.z), tf32r(v.w));
        }
        __syncthreads();
        if (kc + 32 < kend) {
            int kn = kc + 32;
#pragma unroll
            for (int i = 0; i < 4; i++) {
                int f = tid + i * 256, m = f >> 3, k4 = f & 7;
                int gm = bm + m; if (gm >= M) gm = M - 1;
                apf[i] = *(const float4*)(A + (size_t)gm * lda + kn + k4 * 4);
            }
#pragma unroll
            for (int i = 0; i < 2; i++) {
                int f = tid + i * 256, kr = f >> 4, n4 = f & 15;
                bpf[i] = *(const float4*)(B + (size_t)(kn + kr) * ldb + bn + n4 * 4);
            }
        }
        const unsigned* Asu = (const unsigned*)As;
        const unsigned* Bsu = (const unsigned*)Bs;
        int r = lane >> 2, cq = lane & 3;
#pragma unroll
        for (int kk = 0; kk < 4; kk++) {
            unsigned a[2][4], bf[4][2];
#pragma unroll
            for (int t = 0; t < 2; t++) {
                int base = (wm + t * 16 + r) * 44 + kk * 8 + cq;
                a[t][0] = Asu[base]; a[t][1] = Asu[base + 8 * 44];
                a[t][2] = Asu[base + 4]; a[t][3] = Asu[base + 8 * 44 + 4];
            }
#pragma unroll
            for (int j = 0; j < 4; j++) {
                int base = (kk * 8 + cq) * 72 + wn + j * 8 + r;
                bf[j][0] = Bsu[base]; bf[j][1] = Bsu[base + 4 * 72];
            }
#pragma unroll
            for (int t = 0; t < 2; t++)
#pragma unroll
                for (int j = 0; j < 4; j++)
                    mma8(acc[t][j], a[t], bf[j]);
        }
        __syncthreads();
    }
    int r = lane >> 2, cq = lane & 3;
#pragma unroll
    for (int t = 0; t < 2; t++) {
#pragma unroll
        for (int j = 0; j < 4; j++) {
            int row0 = bm + wm + t * 16 + r;
            int col = bn + wn + j * 8 + cq * 2;
            float* ac = acc[t][j];
            float b0 = bias ? bias[col] : 0.0f;
            float b1 = bias ? bias[col + 1] : 0.0f;
            if (STORE_T) {
                if (row0 < M) {
                    C[(size_t)col * ldc + row0] = ac[0] + b0;
                    C[(size_t)(col + 1) * ldc + row0] = ac[1] + b1;
                }
                if (row0 + 8 < M) {
                    C[(size_t)col * ldc + row0 + 8] = ac[2] + b0;
                    C[(size_t)(col + 1) * ldc + row0 + 8] = ac[3] + b1;
                }
            } else if (HOUT) {
                __half* Ch = (__half*)C;
                if (row0 < M)
                    *(__half2*)(Ch + (size_t)row0 * ldc + col) = __floats2half2_rn(ac[0] + b0, ac[1] + b1);
                if (row0 + 8 < M)
                    *(__half2*)(Ch + (size_t)(row0 + 8) * ldc + col) = __floats2half2_rn(ac[2] + b0, ac[3] + b1);
            } else {
                if (row0 < M)
                    *(float2*)(C + (size_t)row0 * ldc + col) = make_float2(ac[0] + b0, ac[1] + b1);
                if (row0 + 8 < M)
                    *(float2*)(C + (size_t)(row0 + 8) * ldc + col) = make_float2(ac[2] + b0, ac[3] + b1);
            }
        }
    }
}

// ---------------- fp16 GEMM: A fp16 [M][K], B fp16 [64][K] (batch rows) ------
// C fp32 = A @ B^T_over_batch ; tile 128m x 64n x 32k, 8 warps (4m x 2n, 32x32)
template<bool STORE_T>
__global__ void __launch_bounds__(256)
gemm_h(const __half* __restrict__ A, const __half* __restrict__ B,
       const float* __restrict__ bias, float* __restrict__ C,
       int M, int K, int lda, int ldb, int ldc, size_t zstride)
{
    __shared__ __half As[128 * 40];   // [m][k] stride 40 halves
    __shared__ __half Bs[64 * 40];    // [n][k] stride 40

    int tid = threadIdx.x;
    int lane = tid & 31, w = tid >> 5;
    int wm = (w & 3) * 32, wn = (w >> 2) * 32;
    int bm = blockIdx.y * 128;
    int kper = K / gridDim.z;
    int k0 = blockIdx.z * kper, kend = k0 + kper;
    C += (size_t)blockIdx.z * zstride;

    float acc[2][4][4] = {};
    uint4 apf[2], bpf;
    {
        int kc = k0;
#pragma unroll
        for (int i = 0; i < 2; i++) {
            int f = tid + i * 256, row = f >> 2, v = f & 3;
            int gm = bm + row; if (gm >= M) gm = M - 1;
            apf[i] = *(const uint4*)(A + (size_t)gm * lda + kc + v * 8);
        }
        { int n = tid >> 2, v = tid & 3;
          bpf = *(const uint4*)(B + (size_t)n * ldb + kc + v * 8); }
    }
    for (int kc = k0; kc < kend; kc += 32) {
#pragma unroll
        for (int i = 0; i < 2; i++) {
            int f = tid + i * 256, row = f >> 2, v = f & 3;
            *(uint4*)&As[row * 40 + v * 8] = apf[i];
        }
        { int n = tid >> 2, v = tid & 3;
          *(uint4*)&Bs[n * 40 + v * 8] = bpf; }
        __syncthreads();
        if (kc + 32 < kend) {
            int kn = kc + 32;
#pragma unroll
            for (int i = 0; i < 2; i++) {
                int f = tid + i * 256, row = f >> 2, v = f & 3;
                int gm = bm + row; if (gm >= M) gm = M - 1;
                apf[i] = *(const uint4*)(A + (size_t)gm * lda + kn + v * 8);
            }
            { int n = tid >> 2, v = tid & 3;
              bpf = *(const uint4*)(B + (size_t)n * ldb + kn + v * 8); }
        }
        const unsigned* Au = (const unsigned*)As;
        const unsigned* Bu = (const unsigned*)Bs;
        int r = lane >> 2, cq = lane & 3;
#pragma unroll
        for (int kk = 0; kk < 2; kk++) {
            unsigned a[2][4], bf[4][2];
#pragma unroll
            for (int t = 0; t < 2; t++) {
                int base = (wm + t * 16 + r) * 20 + kk * 8 + cq;
                a[t][0] = Au[base]; a[t][1] = Au[base + 160];
                a[t][2] = Au[base + 4]; a[t][3] = Au[base + 164];
            }
#pragma unroll
            for (int j = 0; j < 4; j++) {
                int base = (wn + j * 8 + r) * 20 + kk * 8 + cq;
                bf[j][0] = Bu[base]; bf[j][1] = Bu[base + 4];
            }
#pragma unroll
            for (int t = 0; t < 2; t++)
#pragma unroll
                for (int j = 0; j < 4; j++)
                    mma16(acc[t][j], a[t], bf[j]);
        }
        __syncthreads();
    }
    int r = lane >> 2, cq = lane & 3;
#pragma unroll
    for (int t = 0; t < 2; t++) {
#pragma unroll
        for (int j = 0; j < 4; j++) {
            int row0 = bm + wm + t * 16 + r;
            int col = wn + j * 8 + cq * 2;
            float* ac = acc[t][j];
            float b0 = bias ? bias[col] : 0.0f;
            float b1 = bias ? bias[col + 1] : 0.0f;
            if (STORE_T) {
                if (row0 < M) {
                    C[(size_t)col * ldc + row0] = ac[0] + b0;
                    C[(size_t)(col + 1) * ldc + row0] = ac[1] + b1;
                }
                if (row0 + 8 < M) {
                    C[(size_t)col * ldc + row0 + 8] = ac[2] + b0;
                    C[(size_t)(col + 1) * ldc + row0 + 8] = ac[3] + b1;
                }
            } else {
                if (row0 < M)
                    *(float2*)(C + (size_t)row0 * ldc + col) = make_float2(ac[0] + b0, ac[1] + b1);
                if (row0 + 8 < M)
                    *(float2*)(C + (size_t)(row0 + 8) * ldc + col) = make_float2(ac[2] + b0, ac[3] + b1);
            }
        }
    }
}

// ---------------- fused GRU layer, fp16 operands, full 64-batch tile ---------
// grid 64 (j-chunks of 16), block 192 (6 warps: 3 gates x 2 n-halves, 16x32).
__global__ void __launch_bounds__(192)
gru_h(const __half* __restrict__ Wi, const __half* __restrict__ Wh,
      const __half* __restrict__ x16, const __half* __restrict__ hin16,
      const float* __restrict__ hin32, float* __restrict__ hout32,
      __half* __restrict__ hout16, const float* __restrict__ gix,
      const float* __restrict__ bi, const float* __restrict__ bh)
{
    __shared__ float pool[6240];
    __half* As = (__half*)pool;            // 2 mats * 48 * 40 halves
    __half* Bs = (__half*)(pool + 1920);   // 2 mats * 64 * 40 halves
    float* gi_s = pool;                    // 48*65 (reused after k-loop)
    float* gh_s = pool + 3120;

    int tid = threadIdx.x;
    int lane = tid & 31, w = tid >> 5;
    int J0 = blockIdx.x * 16;
    int g = w >> 1, nh = w & 1;
    int r = lane >> 2, cq = lane & 3;

    float accI[4][4] = {}, accH[4][4] = {};
    uint4 pf[5];

#pragma unroll
    for (int i = 0; i < 5; i++) {
        int f = tid + i * 192;
        if (f < 384) {
            int mat = f >= 192; int ff = f - (mat ? 192 : 0);
            int row = ff >> 2, v = ff & 3;
            int grow = ((row >> 4) << 10) + J0 + (row & 15);
            const __half* src = (mat ? Wh : Wi) + (size_t)grow * 1024 + v * 8;
            pf[i] = *(const uint4*)src;
        } else if (f < 896) {
            int fb = f - 384; int mat = fb >= 256; int f2 = fb & 255;
            int n = f2 >> 2, v = f2 & 3;
            const __half* src = (mat ? hin16 : x16) + (size_t)n * 1024 + v * 8;
            pf[i] = *(const uint4*)src;
        }
    }

    for (int kc = 0; kc < 1024; kc += 32) {
#pragma unroll
        for (int i = 0; i < 5; i++) {
            int f = tid + i * 192;
            if (f < 384) {
                int mat = f >= 192; int ff = f - (mat ? 192 : 0);
                int row = ff >> 2, v = ff & 3;
                *(uint4*)&As[mat * 1920 + row * 40 + v * 8] = pf[i];
            } else if (f < 896) {
                int fb = f - 384; int mat = fb >= 256; int f2 = fb & 255;
                int n = f2 >> 2, v = f2 & 3;
                *(uint4*)&Bs[mat * 2560 + n * 40 + v * 8] = pf[i];
            }
        }
        __syncthreads();
        if (kc + 32 < 1024) {
            int kn = kc + 32;
#pragma unroll
            for (int i = 0; i < 5; i++) {
                int f = tid + i * 192;
                if (f < 384) {
                    int mat = f >= 192; int ff = f - (mat ? 192 : 0);
                    int row = ff >> 2, v = ff & 3;
                    int grow = ((row >> 4) << 10) + J0 + (row & 15);
                    const __half* src = (mat ? Wh : Wi) + (size_t)grow * 1024 + kn + v * 8;
                    pf[i] = *(const uint4*)src;
                } else if (f < 896) {
                    int fb = f - 384; int mat = fb >= 256; int f2 = fb & 255;
                    int n = f2 >> 2, v = f2 & 3;
                    const __half* src = (mat ? hin16 : x16) + (size_t)n * 1024 + kn + v * 8;
                    pf[i] = *(const uint4*)src;
                }
            }
        }
        const unsigned* Au = (const unsigned*)As;
        const unsigned* Bu = (const unsigned*)Bs;
#pragma unroll
        for (int kk = 0; kk < 2; kk++) {
            unsigned ai[4], ah[4];
            int abase = (g * 16 + r) * 20 + kk * 8 + cq;
            ai[0] = Au[abase]; ai[1] = Au[abase + 160];
            ai[2] = Au[abase + 4]; ai[3] = Au[abase + 164];
            ah[0] = Au[abase + 960]; ah[1] = Au[abase + 1120];
            ah[2] = Au[abase + 964]; ah[3] = Au[abase + 1124];
            unsigned bx[4][2], bh2[4][2];
#pragma unroll
            for (int j = 0; j < 4; j++) {
                int bbase = (nh * 32 + j * 8 + r) * 20 + kk * 8 + cq;
                bx[j][0] = Bu[bbase]; bx[j][1] = Bu[bbase + 4];
                bh2[j][0] = Bu[bbase + 1280]; bh2[j][1] = Bu[bbase + 1284];
            }
#pragma unroll
            for (int j = 0; j < 4; j++) { mma16(accI[j], ai, bx[j]); mma16(accH[j], ah, bh2[j]); }
        }
        __syncthreads();
    }

    // stage gates to smem (pool reuse), then elementwise update
#pragma unroll
    for (int j = 0; j < 4; j++) {
        int row0 = g * 16 + r;
        int col = nh * 32 + j * 8 + cq * 2;
        gi_s[row0 * 65 + col] = accI[j][0];       gi_s[row0 * 65 + col + 1] = accI[j][1];
        gi_s[(row0 + 8) * 65 + col] = accI[j][2]; gi_s[(row0 + 8) * 65 + col + 1] = accI[j][3];
        gh_s[row0 * 65 + col] = accH[j][0];       gh_s[row0 * 65 + col + 1] = accH[j][1];
        gh_s[(row0 + 8) * 65 + col] = accH[j][2]; gh_s[(row0 + 8) * 65 + col + 1] = accH[j][3];
    }
    __syncthreads();
    for (int idx = tid; idx < 1024; idx += 192) {
        int jj = idx & 15, bb = idx >> 4;
        int j = J0 + jj;
        float ir = gi_s[jj * 65 + bb] + bi[j];
        float iz = gi_s[(16 + jj) * 65 + bb] + bi[1024 + j];
        float in_ = gi_s[(32 + jj) * 65 + bb] + bi[2048 + j];
        if (gix) {
            ir  += gix[(size_t)j * 960 + bb];
            iz  += gix[(size_t)(1024 + j) * 960 + bb];
            in_ += gix[(size_t)(2048 + j) * 960 + bb];
        }
        float hr = gh_s[jj * 65 + bb] + bh[j];
        float hz = gh_s[(16 + jj) * 65 + bb] + bh[1024 + j];
        float hn = gh_s[(32 + jj) * 65 + bb] + bh[2048 + j];
        float rr = 1.0f / (1.0f + expf(-(ir + hr)));
        float zz = 1.0f / (1.0f + expf(-(iz + hz)));
        float nn = tanhf(in_ + rr * hn);
        float hold = hin32[(size_t)j * 64 + bb];
        float val = (1.0f - zz) * nn + zz * hold;
        hout32[(size_t)j * 64 + bb] = val;
        hout16[(size_t)bb * 1024 + j] = __float2half_rn(val);
    }
}

// ---------------- misc kernels ----------------
__global__ void zerok(float* p, int n) {
    int i = blockIdx.x * 256 + threadIdx.x;
    if (i < n) p[i] = 0.0f;
}

__global__ void gather_emb(const float* __restrict__ emb,
                           const int* __restrict__ captions,
                           const int* __restrict__ sos,
                           float* __restrict__ xemb) {
    int m = blockIdx.x;
    int b = m & 63, t = m >> 6;
    int tok = (t == 0) ? sos[0] : captions[b * 16 + t];
    const float4* src = (const float4*)(emb + (size_t)tok * CE);
    float4* dst = (float4*)(xemb + (size_t)m * CE);
    dst[threadIdx.x] = src[threadIdx.x];
}

// out[Cc][R] (half) = in[R][Cc] (float) transposed
__global__ void transpose_h(const float* __restrict__ in, __half* __restrict__ out,
                            int R, int Cc) {
    __shared__ float t[32][33];
    int c = blockIdx.x * 32 + threadIdx.x;
    int r = blockIdx.y * 32 + threadIdx.y;
#pragma unroll
    for (int i = 0; i < 4; i++) {
        int rr = r + i * 8;
        if (rr < R && c < Cc) t[threadIdx.y + i * 8][threadIdx.x] = in[(size_t)rr * Cc + c];
    }
    __syncthreads();
    int c2 = blockIdx.y * 32 + threadIdx.x;
    int r2 = blockIdx.x * 32 + threadIdx.y;
#pragma unroll
    for (int i = 0; i < 4; i++) {
        int rr = r2 + i * 8;
        if (rr < Cc && c2 < R)
            out[(size_t)rr * R + c2] = __float2half_rn(t[threadIdx.x][threadIdx.y + i * 8]);
    }
}

__global__ void conv_h(const float* __restrict__ in, __half* __restrict__ out, int n2) {
    int i = blockIdx.x * 256 + threadIdx.x;   // over float2 pairs
    if (i < n2) {
        float2 v = ((const float2*)in)[i];
        ((__half2*)out)[i] = __floats2half2_rn(v.x, v.y);
    }
}

// Wi0 ctx-half: out[r][c] = in[r][1024 + c], r<3072, c<1024
__global__ void conv_wi0c(const float* __restrict__ in, __half* __restrict__ out) {
    int i = blockIdx.x * 256 + threadIdx.x;   // over half2 pairs: 3072*512
    int r = i >> 9, c2 = (i & 511) * 2;
    float2 v = *(const float2*)(in + (size_t)r * 2048 + 1024 + c2);
    ((__half2*)out)[i] = __floats2half2_rn(v.x, v.y);
}

__global__ void qsum_kernel(const float* __restrict__ qp, const float* __restrict__ bq,
                            float* __restrict__ qs) {
    int idx = blockIdx.x * 256 + threadIdx.x;
    int h = idx & 1023;
    float s = bq[h];
#pragma unroll
    for (int z = 0; z < 8; z++) s += qp[z * (CB * CH) + idx];
    qs[idx] = s;
}

// e[b,s] = bv + sum_h v[h]*tanh(qs[b,h] + keys16[b,s,h])
__global__ void e_kernel(const float* __restrict__ qs, const __half* __restrict__ keys16,
                         const float* __restrict__ v, const float* __restrict__ bv,
                         float* __restrict__ e) {
    int s = blockIdx.x, b = blockIdx.y, tid = threadIdx.x;
    const __half2* k2 = (const __half2*)(keys16 + ((size_t)b * CS + s) * CH);
    const float2* q2 = (const float2*)(qs + (size_t)b * CH);
    const float2* v2 = (const float2*)v;
    float partial = 0.0f;
#pragma unroll
    for (int i = 0; i < 4; i++) {
        int ii = tid + i * 128;
        __half2 kh = k2[ii];
        float2 q = q2[ii], vv = v2[ii];
        partial += vv.x * fast_tanh(q.x + __low2float(kh));
        partial += vv.y * fast_tanh(q.y + __high2float(kh));
    }
#pragma unroll
    for (int o = 16; o > 0; o >>= 1) partial += __shfl_xor_sync(0xffffffffu, partial, o);
    __shared__ float ws[4];
    if ((tid & 31) == 0) ws[tid >> 5] = partial;
    __syncthreads();
    if (tid == 0) e[b * CS + s] = ws[0] + ws[1] + ws[2] + ws[3] + bv[0];
}

__global__ void softmax_k(const float* __restrict__ e, float* __restrict__ w) {
    int b = blockIdx.x, tid = threadIdx.x;
    __shared__ float sh[256];
    float v = (tid < CS) ? e[b * CS + tid] : -1e30f;
    sh[tid] = v; __syncthreads();
    for (int o = 128; o > 0; o >>= 1) { if (tid < o) sh[tid] = fmaxf(sh[tid], sh[tid + o]); __syncthreads(); }
    float m = sh[0]; __syncthreads();
    float ex = (tid < CS) ? __expf(v - m) : 0.0f;
    sh[tid] = ex; __syncthreads();
    for (int o = 128; o > 0; o >>= 1) { if (tid < o) sh[tid] += sh[tid + o]; __syncthreads(); }
    float s = sh[0];
    if (tid < CS) w[b * CS + tid] = ex / s;
}

// ctx16[b][k] = half( sum_s w[b,s]*feat16[b,s,k] ) ; grid (32, 8), block 256
__global__ void ctx_h(const float* __restrict__ w, const __half* __restrict__ feat16,
                      __half* __restrict__ ctx16) {
    int kk = threadIdx.x & 31, bb = threadIdx.x >> 5;
    int b = blockIdx.y * 8 + bb;
    int kd = blockIdx.x * 32 + kk;    // half2 index, covers 2048/2
    __shared__ float ws[8][200];
    for (int i = threadIdx.x; i < 8 * CS; i += 256)
        ws[i / CS][i % CS] = w[(blockIdx.y * 8 + i / CS) * CS + i % CS];
    __syncthreads();
    const __half2* f2 = (const __half2*)(feat16 + (size_t)b * CS * CK);
    float ax = 0.0f, ay = 0.0f;
#pragma unroll 4
    for (int s = 0; s < CS; s++) {
        __half2 hv = f2[(size_t)s * 1024 + kd];
        float wv = ws[bb][s];
        ax = fmaf(wv, __low2float(hv), ax);
        ay = fmaf(wv, __high2float(hv), ay);
    }
    ((__half2*)(ctx16 + (size_t)b * CK))[kd] = __floats2half2_rn(ax, ay);
}

// reduce fc0 split-K partials [z][j][64] + bias -> ctxH16[b][j] (half)
__global__ void reduce64h(const float* __restrict__ part, const float* __restrict__ bias,
                          __half* __restrict__ out16, int z, size_t zstride) {
    int idx = blockIdx.x * 256 + threadIdx.x;
    int j = idx >> 6, b = idx & 63;
    float s = bias[j];
    for (int zz = 0; zz < z; zz++) s += part[zz * zstride + idx];
    out16[(size_t)b * 1024 + j] = __float2half_rn(s);
}

__global__ void reduce_fc2(const float* __restrict__ p, const float* __restrict__ bias,
                           float* __restrict__ out, int t) {
    int idx = blockIdx.x * 256 + threadIdx.x;
    if (idx >= CB * CV) return;
    int b = idx / CV, v = idx - b * CV;
    float s = bias[v] + p[(size_t)b * 10016 + v] + p[(size_t)CB * 10016 + (size_t)b * 10016 + v];
    out[((size_t)b * CT + t) * CV + v] = s;
}

// ---------------- host launcher ----------------
extern "C" void kernel_launch(void* const* d_in, const int* in_sizes, int n_in,
                              void* d_out, int out_size) {
    const float* features = (const float*)d_in[0];
    const int*   captions = (const int*)d_in[1];
    const int*   sos      = (const int*)d_in[2];
    const float* emb      = (const float*)d_in[3];
    const float* fc1_W    = (const float*)d_in[4];
    const float* fc1_b    = (const float*)d_in[5];
    const float* attn_Wq  = (const float*)d_in[6];
    const float* attn_bq  = (const float*)d_in[7];
    const float* attn_Wk  = (const float*)d_in[8];
    const float* attn_bk  = (const float*)d_in[9];
    const float* attn_v   = (const float*)d_in[10];
    const float* attn_bv  = (const float*)d_in[11];
    const float* fc0_W    = (const float*)d_in[12];
    const float* fc0_b    = (const float*)d_in[13];
    const float* Wi0      = (const float*)d_in[14];
    const float* Wh0      = (const float*)d_in[15];
    const float* bi0      = (const float*)d_in[16];
    const float* bh0      = (const float*)d_in[17];
    const float* WiL      = (const float*)d_in[18];
    const float* WhL      = (const float*)d_in[19];
    const float* biL      = (const float*)d_in[20];
    const float* bhL      = (const float*)d_in[21];
    const float* fc2_W    = (const float*)d_in[22];
    const float* fc2_b    = (const float*)d_in[23];
    float* out = (float*)d_out;

    float* sc = nullptr;
    cudaGetSymbolAddress((void**)&sc, g_scratch);
    float*  xemb   = sc + OFF_XEMB;
    float*  xseqT  = sc + OFF_XSEQT;
    float*  giX    = sc + OFF_GIX;
    __half* keys16 = (__half*)(sc + OFF_KEYS16);
    __half* feat16 = (__half*)(sc + OFF_FEAT16);
    __half* Wq16   = (__half*)(sc + OFF_WQ16);
    __half* fc016  = (__half*)(sc + OFF_FC016);
    __half* fc216  = (__half*)(sc + OFF_FC216);
    __half* Wi0c   = (__half*)(sc + OFF_WI0C);
    __half* Wh016  = (__half*)(sc + OFF_WH016);
    __half* WiL16  = (__half*)(sc + OFF_WIL16);
    __half* WhL16  = (__half*)(sc + OFF_WHL16);
    float*  ebuf   = sc + OFF_E;
    float*  wbuf   = sc + OFF_W;
    float*  qp     = sc + OFF_QP;
    float*  qs     = sc + OFF_QS;
    __half* ctx16  = (__half*)(sc + OFF_CTX16);
    __half* ctxH16 = (__half*)(sc + OFF_CTXH16);
    float*  h32A   = sc + OFF_H32A;
    float*  h32B   = sc + OFF_H32B;
    __half* h16A   = (__half*)(sc + OFF_H16A);
    __half* h16B   = (__half*)(sc + OFF_H16B);
    float*  fc0p   = sc + OFF_FC0P;
    float*  fc2p   = sc + OFF_FC2P;

    zerok<<<1024, 256>>>(h32A, 4 * CB * CH);
    zerok<<<512, 256>>>((float*)h16A, 2 * CB * CH);
    gather_emb<<<CB * CT, 128>>>(emb, captions, sos, xemb);

    // fp16 conversions / transposes
    transpose_h<<<dim3(32, 32), dim3(32, 8)>>>(attn_Wq, Wq16, CH, CH);
    transpose_h<<<dim3(32, 64), dim3(32, 8)>>>(fc0_W, fc016, CK, CH);
    transpose_h<<<dim3((CV + 31) / 32, 32), dim3(32, 8)>>>(fc2_W, fc216, CH, CV);
    conv_wi0c<<<(3072 * 512 + 255) / 256, 256>>>(Wi0, Wi0c);
    conv_h<<<(3072 * 512 + 255) / 256, 256>>>(Wh0, Wh016, 3072 * 512);
    conv_h<<<(3 * 3072 * 512 + 255) / 256, 256>>>(WiL, WiL16, 3 * 3072 * 512);
    conv_h<<<(3 * 3072 * 512 + 255) / 256, 256>>>(WhL, WhL16, 3 * 3072 * 512);
    conv_h<<<(CB * CS * CK / 2 + 255) / 256, 256>>>(features, feat16, CB * CS * CK / 2);

    // xseqT = (xemb @ fc1_W + b)^T (fp32)
    gemm_tf32<true, false><<<dim3(16, 8, 1), 256>>>(xemb, fc1_W, fc1_b, xseqT,
                                                    960, CE, CE, CH, 960, 0);
    // giX = Wi0[:, :1024] @ xseqT (fp32)
    gemm_tf32<false, false><<<dim3(15, 24, 1), 256>>>(Wi0, xseqT, nullptr, giX,
                                                      3 * CH, CH, 2 * CH, 960, 960, 0);
    // keys16 = half(features @ attn_Wk + bk)
    gemm_tf32<false, true><<<dim3(16, 98, 1), 256>>>(features, attn_Wk, attn_bk,
                                                     (float*)keys16,
                                                     CB * CS, CK, CK, CH, CH, 0);

    for (int t = 0; t < CT; t++) {
        float*  cur32 = (t & 1) ? h32B : h32A;
        float*  nxt32 = (t & 1) ? h32A : h32B;
        __half* cur16 = (t & 1) ? h16B : h16A;
        __half* nxt16 = (t & 1) ? h16A : h16B;
        __half* htop16 = cur16 + 3 * CB * CH;      // query state (pre-update)
        __half* htopNew16 = nxt16 + 3 * CB * CH;   // logits state (post-update)

        gemm_h<true><<<dim3(1, 8, 8), 256>>>(Wq16, htop16, nullptr, qp,
                                             CH, CH, CH, CH, CH, (size_t)CB * CH);
        qsum_kernel<<<256, 256>>>(qp, attn_bq, qs);
        e_kernel<<<dim3(CS, CB), 128>>>(qs, keys16, attn_v, attn_bv, ebuf);
        softmax_k<<<CB, 256>>>(ebuf, wbuf);
        ctx_h<<<dim3(32, 8), 256>>>(wbuf, feat16, ctx16);
        gemm_h<false><<<dim3(1, 8, 8), 256>>>(fc016, ctx16, nullptr, fc0p,
                                              CH, CK, CK, CK, 64, (size_t)CB * CH);
        reduce64h<<<256, 256>>>(fc0p, fc0_b, ctxH16, 8, (size_t)CB * CH);

        gru_h<<<64, 192>>>(Wi0c, Wh016, ctxH16, cur16, cur32, nxt32, nxt16,
                           giX + t * 64, bi0, bh0);
        for (int l = 1; l < 4; l++) {
            gru_h<<<64, 192>>>(WiL16 + (size_t)(l - 1) * 3 * CH * CH,
                               WhL16 + (size_t)(l - 1) * 3 * CH * CH,
                               nxt16 + (size_t)(l - 1) * CB * CH,
                               cur16 + (size_t)l * CB * CH,
                               cur32 + (size_t)l * CB * CH,
                               nxt32 + (size_t)l * CB * CH,
                               nxt16 + (size_t)l * CB * CH,
                               nullptr,
                               biL + (size_t)(l - 1) * 3 * CH,
                               bhL + (size_t)(l - 1) * 3 * CH);
        }

        gemm_h<true><<<dim3(1, 79, 2), 256>>>(fc216, htopNew16, nullptr, fc2p,
                                              CV, CH, CH, CH, 10016, (size_t)CB * 10016);
        reduce_fc2<<<(CB * CV + 255) / 256, 256>>>(fc2p, fc2_b, out, t);
    }
}

// round 8
// speedup vs baseline: 1.3967x; 1.2801x over previous
#include <cuda_runtime.h>
#include <cuda_fp16.h>
#include <math.h>

#define CV 10000
#define CE 512
#define CH 1024
#define CK 2048
#define CB 64
#define CS 196
#define CT 15

// ---------------- scratch layout (float units, 16B-aligned) ----------------
#define OFF_XEMB    0u
#define OFF_XSEQT   491520u
#define OFF_GIX     1474560u
#define OFF_KEYS16  4423680u
#define OFF_FEAT16  10846208u
#define OFF_WQ16    23691264u
#define OFF_FC016   24215552u
#define OFF_FC216   25264128u
#define OFF_WI0C    30384128u
#define OFF_WH016   31956992u
#define OFF_WIL16   33529856u
#define OFF_WHL16   38248448u
#define OFF_E       42967040u
#define OFF_QP      42992128u
#define OFF_QS      43516416u
#define OFF_CTX16   43581952u
#define OFF_CTXH16  43647488u
#define OFF_H32A    43680256u
#define OFF_H32B    43942400u
#define OFF_H16A    44204544u
#define OFF_H16B    44335616u
#define OFF_FC0P    44466688u
#define OFF_HALL    44990976u   // [960][1024] halves = 491520 floats
#define SCRATCH_TOTAL 45482496u

__device__ __align__(16) float g_scratch[SCRATCH_TOTAL];

__device__ __forceinline__ float fast_tanh(float x) {
    float e = __expf(2.0f * x);
    return 1.0f - __fdividef(2.0f, 1.0f + e);
}

__device__ __forceinline__ float tf32r(float x) {
    unsigned u;
    asm("cvt.rna.tf32.f32 %0, %1;" : "=r"(u) : "f"(x));
    return __uint_as_float(u);
}

__device__ __forceinline__ void mma8(float* c, const unsigned* a, const unsigned* b) {
    asm volatile(
        "mma.sync.aligned.m16n8k8.row.col.f32.tf32.tf32.f32 "
        "{%0,%1,%2,%3}, {%4,%5,%6,%7}, {%8,%9}, {%0,%1,%2,%3};\n"
        : "+f"(c[0]), "+f"(c[1]), "+f"(c[2]), "+f"(c[3])
        : "r"(a[0]), "r"(a[1]), "r"(a[2]), "r"(a[3]), "r"(b[0]), "r"(b[1]));
}

__device__ __forceinline__ void mma16(float* c, const unsigned* a, const unsigned* b) {
    asm volatile(
        "mma.sync.aligned.m16n8k16.row.col.f32.f16.f16.f32 "
        "{%0,%1,%2,%3}, {%4,%5,%6,%7}, {%8,%9}, {%0,%1,%2,%3};\n"
        : "+f"(c[0]), "+f"(c[1]), "+f"(c[2]), "+f"(c[3])
        : "r"(a[0]), "r"(a[1]), "r"(a[2]), "r"(a[3]), "r"(b[0]), "r"(b[1]));
}

// ---------------- tf32 GEMM (prologue; proven) ----------------
template<bool STORE_T, bool HOUT>
__global__ void __launch_bounds__(256)
gemm_tf32(const float* __restrict__ A, const float* __restrict__ B,
          const float* __restrict__ bias, float* __restrict__ C,
          int M, int K, int lda, int ldb, int ldc, size_t zstride)
{
    __shared__ float As[128 * 44];
    __shared__ float Bs[32 * 72];
    int tid = threadIdx.x;
    int lane = tid & 31, w = tid >> 5;
    int wm = (w & 3) * 32, wn = (w >> 2) * 32;
    int bn = blockIdx.x * 64, bm = blockIdx.y * 128;
    int kper = K / gridDim.z;
    int k0 = blockIdx.z * kper, kend = k0 + kper;
    C += (size_t)blockIdx.z * zstride;

    float acc[2][4][4] = {};
    float4 apf[4], bpf[2];
    {
        int kc = k0;
#pragma unroll
        for (int i = 0; i < 4; i++) {
            int f = tid + i * 256, m = f >> 3, k4 = f & 7;
            int gm = bm + m; if (gm >= M) gm = M - 1;
            apf[i] = *(const float4*)(A + (size_t)gm * lda + kc + k4 * 4);
        }
#pragma unroll
        for (int i = 0; i < 2; i++) {
            int f = tid + i * 256, kr = f >> 4, n4 = f & 15;
            bpf[i] = *(const float4*)(B + (size_t)(kc + kr) * ldb + bn + n4 * 4);
        }
    }
    for (int kc = k0; kc < kend; kc += 32) {
#pragma unroll
        for (int i = 0; i < 4; i++) {
            int f = tid + i * 256, m = f >> 3, k4 = f & 7;
            float4 v = apf[i];
            *(float4*)&As[m * 44 + k4 * 4] =
                make_float4(tf32r(v.x), tf32r(v.y), tf32r(v.z), tf32r(v.w));
        }
#pragma unroll
        for (int i = 0; i < 2; i++) {
            int f = tid + i * 256, kr = f >> 4, n4 = f & 15;
            float4 v = bpf[i];
            *(float4*)&Bs[kr * 72 + n4 * 4] =
                make_float4(tf32r(v.x), tf32r(v.y), tf32r(v.z), tf32r(v.w));
        }
        __syncthreads();
        if (kc + 32 < kend) {
            int kn = kc + 32;
#pragma unroll
            for (int i = 0; i < 4; i++) {
                int f = tid + i * 256, m = f >> 3, k4 = f & 7;
                int gm = bm + m; if (gm >= M) gm = M - 1;
                apf[i] = *(const float4*)(A + (size_t)gm * lda + kn + k4 * 4);
            }
#pragma unroll
            for (int i = 0; i < 2; i++) {
                int f = tid + i * 256, kr = f >> 4, n4 = f & 15;
                bpf[i] = *(const float4*)(B + (size_t)(kn + kr) * ldb + bn + n4 * 4);
            }
        }
        const unsigned* Asu = (const unsigned*)As;
        const unsigned* Bsu = (const unsigned*)Bs;
        int r = lane >> 2, cq = lane & 3;
#pragma unroll
        for (int kk = 0; kk < 4; kk++) {
            unsigned a[2][4], bf[4][2];
#pragma unroll
            for (int t = 0; t < 2; t++) {
                int base = (wm + t * 16 + r) * 44 + kk * 8 + cq;
                a[t][0] = Asu[base]; a[t][1] = Asu[base + 8 * 44];
                a[t][2] = Asu[base + 4]; a[t][3] = Asu[base + 8 * 44 + 4];
            }
#pragma unroll
            for (int j = 0; j < 4; j++) {
                int base = (kk * 8 + cq) * 72 + wn + j * 8 + r;
                bf[j][0] = Bsu[base]; bf[j][1] = Bsu[base + 4 * 72];
            }
#pragma unroll
            for (int t = 0; t < 2; t++)
#pragma unroll
                for (int j = 0; j < 4; j++)
                    mma8(acc[t][j], a[t], bf[j]);
        }
        __syncthreads();
    }
    int r = lane >> 2, cq = lane & 3;
#pragma unroll
    for (int t = 0; t < 2; t++) {
#pragma unroll
        for (int j = 0; j < 4; j++) {
            int row0 = bm + wm + t * 16 + r;
            int col = bn + wn + j * 8 + cq * 2;
            float* ac = acc[t][j];
            float b0 = bias ? bias[col] : 0.0f;
            float b1 = bias ? bias[col + 1] : 0.0f;
            if (STORE_T) {
                if (row0 < M) {
                    C[(size_t)col * ldc + row0] = ac[0] + b0;
                    C[(size_t)(col + 1) * ldc + row0] = ac[1] + b1;
                }
                if (row0 + 8 < M) {
                    C[(size_t)col * ldc + row0 + 8] = ac[2] + b0;
                    C[(size_t)(col + 1) * ldc + row0 + 8] = ac[3] + b1;
                }
            } else if (HOUT) {
                __half* Ch = (__half*)C;
                if (row0 < M)
                    *(__half2*)(Ch + (size_t)row0 * ldc + col) = __floats2half2_rn(ac[0] + b0, ac[1] + b1);
                if (row0 + 8 < M)
                    *(__half2*)(Ch + (size_t)(row0 + 8) * ldc + col) = __floats2half2_rn(ac[2] + b0, ac[3] + b1);
            } else {
                if (row0 < M)
                    *(float2*)(C + (size_t)row0 * ldc + col) = make_float2(ac[0] + b0, ac[1] + b1);
                if (row0 + 8 < M)
                    *(float2*)(C + (size_t)(row0 + 8) * ldc + col) = make_float2(ac[2] + b0, ac[3] + b1);
            }
        }
    }
}

// ---------------- fp16 GEMM vs 64-batch activations (in-loop) ----------------
template<bool STORE_T>
__global__ void __launch_bounds__(256)
gemm_h(const __half* __restrict__ A, const __half* __restrict__ B,
       const float* __restrict__ bias, float* __restrict__ C,
       int M, int K, int lda, int ldb, int ldc, size_t zstride)
{
    __shared__ __half As[128 * 40];
    __shared__ __half Bs[64 * 40];
    int tid = threadIdx.x;
    int lane = tid & 31, w = tid >> 5;
    int wm = (w & 3) * 32, wn = (w >> 2) * 32;
    int bm = blockIdx.y * 128;
    int kper = K / gridDim.z;
    int k0 = blockIdx.z * kper, kend = k0 + kper;
    C += (size_t)blockIdx.z * zstride;

    float acc[2][4][4] = {};
    uint4 apf[2], bpf;
    {
        int kc = k0;
#pragma unroll
        for (int i = 0; i < 2; i++) {
            int f = tid + i * 256, row = f >> 2, v = f & 3;
            int gm = bm + row; if (gm >= M) gm = M - 1;
            apf[i] = *(const uint4*)(A + (size_t)gm * lda + kc + v * 8);
        }
        { int n = tid >> 2, v = tid & 3;
          bpf = *(const uint4*)(B + (size_t)n * ldb + kc + v * 8); }
    }
    for (int kc = k0; kc < kend; kc += 32) {
#pragma unroll
        for (int i = 0; i < 2; i++) {
            int f = tid + i * 256, row = f >> 2, v = f & 3;
            *(uint4*)&As[row * 40 + v * 8] = apf[i];
        }
        { int n = tid >> 2, v = tid & 3;
          *(uint4*)&Bs[n * 40 + v * 8] = bpf; }
        __syncthreads();
        if (kc + 32 < kend) {
            int kn = kc + 32;
#pragma unroll
            for (int i = 0; i < 2; i++) {
                int f = tid + i * 256, row = f >> 2, v = f & 3;
                int gm = bm + row; if (gm >= M) gm = M - 1;
                apf[i] = *(const uint4*)(A + (size_t)gm * lda + kn + v * 8);
            }
            { int n = tid >> 2, v = tid & 3;
              bpf = *(const uint4*)(B + (size_t)n * ldb + kn + v * 8); }
        }
        const unsigned* Au = (const unsigned*)As;
        const unsigned* Bu = (const unsigned*)Bs;
        int r = lane >> 2, cq = lane & 3;
#pragma unroll
        for (int kk = 0; kk < 2; kk++) {
            unsigned a[2][4], bf[4][2];
#pragma unroll
            for (int t = 0; t < 2; t++) {
                int base = (wm + t * 16 + r) * 20 + kk * 8 + cq;
                a[t][0] = Au[base]; a[t][1] = Au[base + 160];
                a[t][2] = Au[base + 4]; a[t][3] = Au[base + 164];
            }
#pragma unroll
            for (int j = 0; j < 4; j++) {
                int base = (wn + j * 8 + r) * 20 + kk * 8 + cq;
                bf[j][0] = Bu[base]; bf[j][1] = Bu[base + 4];
            }
#pragma unroll
            for (int t = 0; t < 2; t++)
#pragma unroll
                for (int j = 0; j < 4; j++)
                    mma16(acc[t][j], a[t], bf[j]);
        }
        __syncthreads();
    }
    int r = lane >> 2, cq = lane & 3;
#pragma unroll
    for (int t = 0; t < 2; t++) {
#pragma unroll
        for (int j = 0; j < 4; j++) {
            int row0 = bm + wm + t * 16 + r;
            int col = wn + j * 8 + cq * 2;
            float* ac = acc[t][j];
            float b0 = bias ? bias[col] : 0.0f;
            float b1 = bias ? bias[col + 1] : 0.0f;
            if (STORE_T) {
                if (row0 < M) {
                    C[(size_t)col * ldc + row0] = ac[0] + b0;
                    C[(size_t)(col + 1) * ldc + row0] = ac[1] + b1;
                }
                if (row0 + 8 < M) {
                    C[(size_t)col * ldc + row0 + 8] = ac[2] + b0;
                    C[(size_t)(col + 1) * ldc + row0 + 8] = ac[3] + b1;
                }
            } else {
                if (row0 < M)
                    *(float2*)(C + (size_t)row0 * ldc + col) = make_float2(ac[0] + b0, ac[1] + b1);
                if (row0 + 8 < M)
                    *(float2*)(C + (size_t)(row0 + 8) * ldc + col) = make_float2(ac[2] + b0, ac[3] + b1);
            }
        }
    }
}

// ---------------- final batched fc2: logits for ALL steps in one GEMM --------
// A = fc216[10000][1024], B = hAll16[960][1024] (n = t*64+b), out[b][t][v].
__global__ void __launch_bounds__(256)
gemm_fc2_final(const __half* __restrict__ A, const __half* __restrict__ B,
               const float* __restrict__ bias, float* __restrict__ out, int M)
{
    __shared__ __half As[128 * 40];
    __shared__ __half Bs[64 * 40];
    int tid = threadIdx.x;
    int lane = tid & 31, w = tid >> 5;
    int wm = (w & 3) * 32, wn = (w >> 2) * 32;
    int bm = blockIdx.y * 128;
    int bn = blockIdx.x * 64;
    B += (size_t)bn * CH;

    float acc[2][4][4] = {};
    uint4 apf[2], bpf;
    {
#pragma unroll
        for (int i = 0; i < 2; i++) {
            int f = tid + i * 256, row = f >> 2, v = f & 3;
            int gm = bm + row; if (gm >= M) gm = M - 1;
            apf[i] = *(const uint4*)(A + (size_t)gm * CH + v * 8);
        }
        { int n = tid >> 2, v = tid & 3;
          bpf = *(const uint4*)(B + (size_t)n * CH + v * 8); }
    }
    for (int kc = 0; kc < CH; kc += 32) {
#pragma unroll
        for (int i = 0; i < 2; i++) {
            int f = tid + i * 256, row = f >> 2, v = f & 3;
            *(uint4*)&As[row * 40 + v * 8] = apf[i];
        }
        { int n = tid >> 2, v = tid & 3;
          *(uint4*)&Bs[n * 40 + v * 8] = bpf; }
        __syncthreads();
        if (kc + 32 < CH) {
            int kn = kc + 32;
#pragma unroll
            for (int i = 0; i < 2; i++) {
                int f = tid + i * 256, row = f >> 2, v = f & 3;
                int gm = bm + row; if (gm >= M) gm = M - 1;
                apf[i] = *(const uint4*)(A + (size_t)gm * CH + kn + v * 8);
            }
            { int n = tid >> 2, v = tid & 3;
              bpf = *(const uint4*)(B + (size_t)n * CH + kn + v * 8); }
        }
        const unsigned* Au = (const unsigned*)As;
        const unsigned* Bu = (const unsigned*)Bs;
        int r = lane >> 2, cq = lane & 3;
#pragma unroll
        for (int kk = 0; kk < 2; kk++) {
            unsigned a[2][4], bf[4][2];
#pragma unroll
            for (int t = 0; t < 2; t++) {
                int base = (wm + t * 16 + r) * 20 + kk * 8 + cq;
                a[t][0] = Au[base]; a[t][1] = Au[base + 160];
                a[t][2] = Au[base + 4]; a[t][3] = Au[base + 164];
            }
#pragma unroll
            for (int j = 0; j < 4; j++) {
                int base = (wn + j * 8 + r) * 20 + kk * 8 + cq;
                bf[j][0] = Bu[base]; bf[j][1] = Bu[base + 4];
            }
#pragma unroll
            for (int t = 0; t < 2; t++)
#pragma unroll
                for (int j = 0; j < 4; j++)
                    mma16(acc[t][j], a[t], bf[j]);
        }
        __syncthreads();
    }
    int r = lane >> 2, cq = lane & 3;
#pragma unroll
    for (int t = 0; t < 2; t++) {
#pragma unroll
        for (int j = 0; j < 4; j++) {
            int row0 = bm + wm + t * 16 + r;
            int n = bn + wn + j * 8 + cq * 2;       // n = tstep*64 + b
            int tt = n >> 6, bb = n & 63;
            float* ac = acc[t][j];
            if (row0 < M) {
                float bz = bias[row0];
                out[((size_t)bb * CT + tt) * CV + row0] = ac[0] + bz;
                out[((size_t)(bb + 1) * CT + tt) * CV + row0] = ac[1] + bz;
            }
            if (row0 + 8 < M) {
                float bz = bias[row0 + 8];
                out[((size_t)bb * CT + tt) * CV + row0 + 8] = ac[2] + bz;
                out[((size_t)(bb + 1) * CT + tt) * CV + row0 + 8] = ac[3] + bz;
            }
        }
    }
}

// ---------------- fused GRU layer, fp16, BK=64, full 64-batch tile -----------
// grid 64 (j-chunks of 16), block 192 (6 warps: 3 gates x 2 n-halves).
__global__ void __launch_bounds__(192)
gru_h(const __half* __restrict__ Wi, const __half* __restrict__ Wh,
      const __half* __restrict__ x16, const __half* __restrict__ hin16,
      const float* __restrict__ hin32, float* __restrict__ hout32,
      __half* __restrict__ hout16, const float* __restrict__ gix,
      const float* __restrict__ bi, const float* __restrict__ bh)
{
    __shared__ float pool[8064];            // 32256 B
    __half* As = (__half*)pool;             // 2 mats * 48 * 72 halves
    __half* Bs = (__half*)(pool + 3456);    // 2 mats * 64 * 72 halves
    float* gi_s = pool;                     // 48*65 (reuse after k-loop)
    float* gh_s = pool + 3120;

    int tid = threadIdx.x;
    int lane = tid & 31, w = tid >> 5;
    int J0 = blockIdx.x * 16;
    int g = w >> 1, nh = w & 1;
    int r = lane >> 2, cq = lane & 3;

    float accI[4][4] = {}, accH[4][4] = {};
    uint4 pf[10];

#pragma unroll
    for (int i = 0; i < 10; i++) {
        int f = tid + i * 192;
        if (f < 768) {
            int mat = f >= 384; int ff = f - mat * 384;
            int row = ff >> 3, v = ff & 7;
            int grow = ((row >> 4) << 10) + J0 + (row & 15);
            pf[i] = *(const uint4*)((mat ? Wh : Wi) + (size_t)grow * 1024 + v * 8);
        } else if (f < 1792) {
            int fb = f - 768; int mat = fb >= 512; int f2 = fb - mat * 512;
            int n = f2 >> 3, v = f2 & 7;
            pf[i] = *(const uint4*)((mat ? hin16 : x16) + (size_t)n * 1024 + v * 8);
        }
    }

    for (int kc = 0; kc < 1024; kc += 64) {
#pragma unroll
        for (int i = 0; i < 10; i++) {
            int f = tid + i * 192;
            if (f < 768) {
                int mat = f >= 384; int ff = f - mat * 384;
                int row = ff >> 3, v = ff & 7;
                *(uint4*)&As[mat * 3456 + row * 72 + v * 8] = pf[i];
            } else if (f < 1792) {
                int fb = f - 768; int mat = fb >= 512; int f2 = fb - mat * 512;
                int n = f2 >> 3, v = f2 & 7;
                *(uint4*)&Bs[mat * 4608 + n * 72 + v * 8] = pf[i];
            }
        }
        __syncthreads();
        if (kc + 64 < 1024) {
            int kn = kc + 64;
#pragma unroll
            for (int i = 0; i < 10; i++) {
                int f = tid + i * 192;
                if (f < 768) {
                    int mat = f >= 384; int ff = f - mat * 384;
                    int row = ff >> 3, v = ff & 7;
                    int grow = ((row >> 4) << 10) + J0 + (row & 15);
                    pf[i] = *(const uint4*)((mat ? Wh : Wi) + (size_t)grow * 1024 + kn + v * 8);
                } else if (f < 1792) {
                    int fb = f - 768; int mat = fb >= 512; int f2 = fb - mat * 512;
                    int n = f2 >> 3, v = f2 & 7;
                    pf[i] = *(const uint4*)((mat ? hin16 : x16) + (size_t)n * 1024 + kn + v * 8);
                }
            }
        }
        const unsigned* Au = (const unsigned*)As;
        const unsigned* Bu = (const unsigned*)Bs;
#pragma unroll
        for (int kk = 0; kk < 4; kk++) {
            unsigned ai[4], ah[4];
            int abase = (g * 16 + r) * 36 + kk * 8 + cq;
            ai[0] = Au[abase]; ai[1] = Au[abase + 288];
            ai[2] = Au[abase + 4]; ai[3] = Au[abase + 292];
            ah[0] = Au[abase + 1728]; ah[1] = Au[abase + 2016];
            ah[2] = Au[abase + 1732]; ah[3] = Au[abase + 2020];
            unsigned bx[4][2], bh2[4][2];
#pragma unroll
            for (int j = 0; j < 4; j++) {
                int bbase = (nh * 32 + j * 8 + r) * 36 + kk * 8 + cq;
                bx[j][0] = Bu[bbase]; bx[j][1] = Bu[bbase + 4];
                bh2[j][0] = Bu[bbase + 2304]; bh2[j][1] = Bu[bbase + 2308];
            }
#pragma unroll
            for (int j = 0; j < 4; j++) { mma16(accI[j], ai, bx[j]); mma16(accH[j], ah, bh2[j]); }
        }
        __syncthreads();
    }

#pragma unroll
    for (int j = 0; j < 4; j++) {
        int row0 = g * 16 + r;
        int col = nh * 32 + j * 8 + cq * 2;
        gi_s[row0 * 65 + col] = accI[j][0];       gi_s[row0 * 65 + col + 1] = accI[j][1];
        gi_s[(row0 + 8) * 65 + col] = accI[j][2]; gi_s[(row0 + 8) * 65 + col + 1] = accI[j][3];
        gh_s[row0 * 65 + col] = accH[j][0];       gh_s[row0 * 65 + col + 1] = accH[j][1];
        gh_s[(row0 + 8) * 65 + col] = accH[j][2]; gh_s[(row0 + 8) * 65 + col + 1] = accH[j][3];
    }
    __syncthreads();
    for (int idx = tid; idx < 1024; idx += 192) {
        int jj = idx & 15, bb = idx >> 4;
        int j = J0 + jj;
        float ir = gi_s[jj * 65 + bb] + bi[j];
        float iz = gi_s[(16 + jj) * 65 + bb] + bi[1024 + j];
        float in_ = gi_s[(32 + jj) * 65 + bb] + bi[2048 + j];
        if (gix) {
            ir  += gix[(size_t)j * 960 + bb];
            iz  += gix[(size_t)(1024 + j) * 960 + bb];
            in_ += gix[(size_t)(2048 + j) * 960 + bb];
        }
        float hr = gh_s[jj * 65 + bb] + bh[j];
        float hz = gh_s[(16 + jj) * 65 + bb] + bh[1024 + j];
        float hn = gh_s[(32 + jj) * 65 + bb] + bh[2048 + j];
        float rr = 1.0f / (1.0f + expf(-(ir + hr)));
        float zz = 1.0f / (1.0f + expf(-(iz + hz)));
        float nn = tanhf(in_ + rr * hn);
        float hold = hin32[(size_t)j * 64 + bb];
        float val = (1.0f - zz) * nn + zz * hold;
        hout32[(size_t)j * 64 + bb] = val;
        hout16[(size_t)bb * 1024 + j] = __float2half_rn(val);
    }
}

// ---------------- misc kernels ----------------
__global__ void zerok(float* p, int n) {
    int i = blockIdx.x * 256 + threadIdx.x;
    if (i < n) p[i] = 0.0f;
}

__global__ void gather_emb(const float* __restrict__ emb,
                           const int* __restrict__ captions,
                           const int* __restrict__ sos,
                           float* __restrict__ xemb) {
    int m = blockIdx.x;
    int b = m & 63, t = m >> 6;
    int tok = (t == 0) ? sos[0] : captions[b * 16 + t];
    const float4* src = (const float4*)(emb + (size_t)tok * CE);
    float4* dst = (float4*)(xemb + (size_t)m * CE);
    dst[threadIdx.x] = src[threadIdx.x];
}

__global__ void transpose_h(const float* __restrict__ in, __half* __restrict__ out,
                            int R, int Cc) {
    __shared__ float t[32][33];
    int c = blockIdx.x * 32 + threadIdx.x;
    int r = blockIdx.y * 32 + threadIdx.y;
#pragma unroll
    for (int i = 0; i < 4; i++) {
        int rr = r + i * 8;
        if (rr < R && c < Cc) t[threadIdx.y + i * 8][threadIdx.x] = in[(size_t)rr * Cc + c];
    }
    __syncthreads();
    int c2 = blockIdx.y * 32 + threadIdx.x;
    int r2 = blockIdx.x * 32 + threadIdx.y;
#pragma unroll
    for (int i = 0; i < 4; i++) {
        int rr = r2 + i * 8;
        if (rr < Cc && c2 < R)
            out[(size_t)rr * R + c2] = __float2half_rn(t[threadIdx.x][threadIdx.y + i * 8]);
    }
}

__global__ void conv_h(const float* __restrict__ in, __half* __restrict__ out, int n2) {
    int i = blockIdx.x * 256 + threadIdx.x;
    if (i < n2) {
        float2 v = ((const float2*)in)[i];
        ((__half2*)out)[i] = __floats2half2_rn(v.x, v.y);
    }
}

__global__ void conv_wi0c(const float* __restrict__ in, __half* __restrict__ out) {
    int i = blockIdx.x * 256 + threadIdx.x;
    int r = i >> 9, c2 = (i & 511) * 2;
    float2 v = *(const float2*)(in + (size_t)r * 2048 + 1024 + c2);
    ((__half2*)out)[i] = __floats2half2_rn(v.x, v.y);
}

__global__ void qsum_kernel(const float* __restrict__ qp, const float* __restrict__ bq,
                            float* __restrict__ qs) {
    int idx = blockIdx.x * 256 + threadIdx.x;
    int h = idx & 1023;
    float s = bq[h];
#pragma unroll
    for (int z = 0; z < 8; z++) s += qp[z * (CB * CH) + idx];
    qs[idx] = s;
}

__global__ void e_kernel(const float* __restrict__ qs, const __half* __restrict__ keys16,
                         const float* __restrict__ v, const float* __restrict__ bv,
                         float* __restrict__ e) {
    int s = blockIdx.x, b = blockIdx.y, tid = threadIdx.x;
    const __half2* k2 = (const __half2*)(keys16 + ((size_t)b * CS + s) * CH);
    const float2* q2 = (const float2*)(qs + (size_t)b * CH);
    const float2* v2 = (const float2*)v;
    float partial = 0.0f;
#pragma unroll
    for (int i = 0; i < 4; i++) {
        int ii = tid + i * 128;
        __half2 kh = k2[ii];
        float2 q = q2[ii], vv = v2[ii];
        partial += vv.x * fast_tanh(q.x + __low2float(kh));
        partial += vv.y * fast_tanh(q.y + __high2float(kh));
    }
#pragma unroll
    for (int o = 16; o > 0; o >>= 1) partial += __shfl_xor_sync(0xffffffffu, partial, o);
    __shared__ float ws[4];
    if ((tid & 31) == 0) ws[tid >> 5] = partial;
    __syncthreads();
    if (tid == 0) e[b * CS + s] = ws[0] + ws[1] + ws[2] + ws[3] + bv[0];
}

// fused softmax + context: grid (32, 8), block 256 (8 warps; warp w owns b)
__global__ void ctxsm_h(const float* __restrict__ e, const __half* __restrict__ feat16,
                        __half* __restrict__ ctx16) {
    __shared__ float ws[8][200];
    int tid = threadIdx.x;
    int lane = tid & 31, w = tid >> 5;
    int b = blockIdx.y * 8 + w;

    // per-warp softmax over 196 energies
    float ev[7];
    float mx = -1e30f;
#pragma unroll
    for (int i = 0; i < 7; i++) {
        int s = lane + i * 32;
        ev[i] = (s < CS) ? e[b * CS + s] : -1e30f;
        mx = fmaxf(mx, ev[i]);
    }
#pragma unroll
    for (int o = 16; o > 0; o >>= 1) mx = fmaxf(mx, __shfl_xor_sync(0xffffffffu, mx, o));
    float sum = 0.0f;
#pragma unroll
    for (int i = 0; i < 7; i++) {
        ev[i] = (lane + i * 32 < CS) ? __expf(ev[i] - mx) : 0.0f;
        sum += ev[i];
    }
#pragma unroll
    for (int o = 16; o > 0; o >>= 1) sum += __shfl_xor_sync(0xffffffffu, sum, o);
    float inv = __fdividef(1.0f, sum);
#pragma unroll
    for (int i = 0; i < 7; i++) {
        int s = lane + i * 32;
        if (s < CS) ws[w][s] = ev[i] * inv;
    }
    __syncwarp();

    // context accumulation: warp w handles b; lanes cover 32 half2 columns
    int kd = blockIdx.x * 32 + lane;
    const __half2* f2 = (const __half2*)(feat16 + (size_t)b * CS * CK);
    float ax = 0.0f, ay = 0.0f;
#pragma unroll 4
    for (int s = 0; s < CS; s++) {
        __half2 hv = f2[(size_t)s * 1024 + kd];
        float wv = ws[w][s];
        ax = fmaf(wv, __low2float(hv), ax);
        ay = fmaf(wv, __high2float(hv), ay);
    }
    ((__half2*)(ctx16 + (size_t)b * CK))[kd] = __floats2half2_rn(ax, ay);
}

__global__ void reduce64h(const float* __restrict__ part, const float* __restrict__ bias,
                          __half* __restrict__ out16, int z, size_t zstride) {
    int idx = blockIdx.x * 256 + threadIdx.x;
    int j = idx >> 6, b = idx & 63;
    float s = bias[j];
    for (int zz = 0; zz < z; zz++) s += part[zz * zstride + idx];
    out16[(size_t)b * 1024 + j] = __float2half_rn(s);
}

// ---------------- host launcher ----------------
extern "C" void kernel_launch(void* const* d_in, const int* in_sizes, int n_in,
                              void* d_out, int out_size) {
    const float* features = (const float*)d_in[0];
    const int*   captions = (const int*)d_in[1];
    const int*   sos      = (const int*)d_in[2];
    const float* emb      = (const float*)d_in[3];
    const float* fc1_W    = (const float*)d_in[4];
    const float* fc1_b    = (const float*)d_in[5];
    const float* attn_Wq  = (const float*)d_in[6];
    const float* attn_bq  = (const float*)d_in[7];
    const float* attn_Wk  = (const float*)d_in[8];
    const float* attn_bk  = (const float*)d_in[9];
    const float* attn_v   = (const float*)d_in[10];
    const float* attn_bv  = (const float*)d_in[11];
    const float* fc0_W    = (const float*)d_in[12];
    const float* fc0_b    = (const float*)d_in[13];
    const float* Wi0      = (const float*)d_in[14];
    const float* Wh0      = (const float*)d_in[15];
    const float* bi0      = (const float*)d_in[16];
    const float* bh0      = (const float*)d_in[17];
    const float* WiL      = (const float*)d_in[18];
    const float* WhL      = (const float*)d_in[19];
    const float* biL      = (const float*)d_in[20];
    const float* bhL      = (const float*)d_in[21];
    const float* fc2_W    = (const float*)d_in[22];
    const float* fc2_b    = (const float*)d_in[23];
    float* out = (float*)d_out;

    float* sc = nullptr;
    cudaGetSymbolAddress((void**)&sc, g_scratch);
    float*  xemb   = sc + OFF_XEMB;
    float*  xseqT  = sc + OFF_XSEQT;
    float*  giX    = sc + OFF_GIX;
    __half* keys16 = (__half*)(sc + OFF_KEYS16);
    __half* feat16 = (__half*)(sc + OFF_FEAT16);
    __half* Wq16   = (__half*)(sc + OFF_WQ16);
    __half* fc016  = (__half*)(sc + OFF_FC016);
    __half* fc216  = (__half*)(sc + OFF_FC216);
    __half* Wi0c   = (__half*)(sc + OFF_WI0C);
    __half* Wh016  = (__half*)(sc + OFF_WH016);
    __half* WiL16  = (__half*)(sc + OFF_WIL16);
    __half* WhL16  = (__half*)(sc + OFF_WHL16);
    float*  ebuf   = sc + OFF_E;
    float*  qp     = sc + OFF_QP;
    float*  qs     = sc + OFF_QS;
    __half* ctx16  = (__half*)(sc + OFF_CTX16);
    __half* ctxH16 = (__half*)(sc + OFF_CTXH16);
    float*  h32A   = sc + OFF_H32A;
    float*  h32B   = sc + OFF_H32B;
    __half* h16A   = (__half*)(sc + OFF_H16A);
    __half* h16B   = (__half*)(sc + OFF_H16B);
    float*  fc0p   = sc + OFF_FC0P;
    __half* hAll16 = (__half*)(sc + OFF_HALL);
    __half* zero16 = h16A + 3 * CB * CH;   // stays zero (layer-3 h16 now goes to hAll16)

    zerok<<<1024, 256>>>(h32A, 4 * CB * CH);
    zerok<<<512, 256>>>((float*)h16A, 2 * CB * CH);
    gather_emb<<<CB * CT, 128>>>(emb, captions, sos, xemb);

    transpose_h<<<dim3(32, 32), dim3(32, 8)>>>(attn_Wq, Wq16, CH, CH);
    transpose_h<<<dim3(32, 64), dim3(32, 8)>>>(fc0_W, fc016, CK, CH);
    transpose_h<<<dim3((CV + 31) / 32, 32), dim3(32, 8)>>>(fc2_W, fc216, CH, CV);
    conv_wi0c<<<(3072 * 512 + 255) / 256, 256>>>(Wi0, Wi0c);
    conv_h<<<(3072 * 512 + 255) / 256, 256>>>(Wh0, Wh016, 3072 * 512);
    conv_h<<<(3 * 3072 * 512 + 255) / 256, 256>>>(WiL, WiL16, 3 * 3072 * 512);
    conv_h<<<(3 * 3072 * 512 + 255) / 256, 256>>>(WhL, WhL16, 3 * 3072 * 512);
    conv_h<<<(CB * CS * CK / 2 + 255) / 256, 256>>>(features, feat16, CB * CS * CK / 2);

    gemm_tf32<true, false><<<dim3(16, 8, 1), 256>>>(xemb, fc1_W, fc1_b, xseqT,
                                                    960, CE, CE, CH, 960, 0);
    gemm_tf32<false, false><<<dim3(15, 24, 1), 256>>>(Wi0, xseqT, nullptr, giX,
                                                      3 * CH, CH, 2 * CH, 960, 960, 0);
    gemm_tf32<false, true><<<dim3(16, 98, 1), 256>>>(features, attn_Wk, attn_bk,
                                                     (float*)keys16,
                                                     CB * CS, CK, CK, CH, CH, 0);

    for (int t = 0; t < CT; t++) {
        float*  cur32 = (t & 1) ? h32B : h32A;
        float*  nxt32 = (t & 1) ? h32A : h32B;
        __half* cur16 = (t & 1) ? h16B : h16A;
        __half* nxt16 = (t & 1) ? h16A : h16B;
        const __half* htop16 = (t == 0) ? zero16 : hAll16 + (size_t)(t - 1) * CB * CH;

        gemm_h<true><<<dim3(1, 8, 8), 256>>>(Wq16, htop16, nullptr, qp,
                                             CH, CH, CH, CH, CH, (size_t)CB * CH);
        qsum_kernel<<<256, 256>>>(qp, attn_bq, qs);
        e_kernel<<<dim3(CS, CB), 128>>>(qs, keys16, attn_v, attn_bv, ebuf);
        ctxsm_h<<<dim3(32, 8), 256>>>(ebuf, feat16, ctx16);
        gemm_h<false><<<dim3(1, 8, 8), 256>>>(fc016, ctx16, nullptr, fc0p,
                                              CH, CK, CK, CK, 64, (size_t)CB * CH);
        reduce64h<<<256, 256>>>(fc0p, fc0_b, ctxH16, 8, (size_t)CB * CH);

        gru_h<<<64, 192>>>(Wi0c, Wh016, ctxH16, cur16, cur32, nxt32, nxt16,
                           giX + t * 64, bi0, bh0);
        for (int l = 1; l < 3; l++) {
            gru_h<<<64, 192>>>(WiL16 + (size_t)(l - 1) * 3 * CH * CH,
                               WhL16 + (size_t)(l - 1) * 3 * CH * CH,
                               nxt16 + (size_t)(l - 1) * CB * CH,
                               cur16 + (size_t)l * CB * CH,
                               cur32 + (size_t)l * CB * CH,
                               nxt32 + (size_t)l * CB * CH,
                               nxt16 + (size_t)l * CB * CH,
                               nullptr,
                               biL + (size_t)(l - 1) * 3 * CH,
                               bhL + (size_t)(l - 1) * 3 * CH);
        }
        // layer 3: fp16 state goes into hAll16[t] (consumed by next step's qp + final fc2)
        gru_h<<<64, 192>>>(WiL16 + (size_t)2 * 3 * CH * CH,
                           WhL16 + (size_t)2 * 3 * CH * CH,
                           nxt16 + (size_t)2 * CB * CH,
                           htop16,
                           cur32 + (size_t)3 * CB * CH,
                           nxt32 + (size_t)3 * CB * CH,
                           hAll16 + (size_t)t * CB * CH,
                           nullptr,
                           biL + (size_t)2 * 3 * CH,
                           bhL + (size_t)2 * 3 * CH);
    }

    // all logits in one batched GEMM
    gemm_fc2_final<<<dim3(15, 79), 256>>>(fc216, hAll16, fc2_b, out, CV);
}